// round 3
// baseline (speedup 1.0000x reference)
#include <cuda_runtime.h>
#include <cuda_bf16.h>
#include <cstdint>
#include <cstddef>

// StreamingConv == GEMM: out[b,o] = sum_kk A[b,kk] * W[o,kk]
// A = curr_input [256 x 16384] fp32, W = weight [1024 x 16384] fp32, both K-contiguous.
//
// sm_103 (non-'a' PTX target) path: mma.sync bf16 (HMMA) with fp32 hi/lo split
// (3 MMAs), tile 128x256, split-K=16, double-buffered SMEM, deterministic reduce.

#define BATCH   256
#define COUT    1024
#define KTOT    16384
#define TM      128
#define TN      256
#define NSPLIT  16
#define KLEN    (KTOT / NSPLIT)   // 1024
#define CHUNK   64
#define NCHUNK  (KLEN / CHUNK)    // 16

// Split-K partials (deterministic reduction, no atomics)
__device__ float g_part[NSPLIT][BATCH * COUT];

// ---- SMEM layout: per stage: A_hi 16K | A_lo 16K | B_hi 32K | B_lo 32K = 96K
#define STAGE_BYTES 98304
#define OFF_AHI 0
#define OFF_ALO 16384
#define OFF_BHI 32768
#define OFF_BLO 65536
#define SMEM_TOTAL (2 * STAGE_BYTES)   // 196608

// 128B-row swizzle, 16B atoms: bits[6:4] ^= bits[9:7]
#define SWZ(o) ((o) ^ (((o) >> 3) & 0x70))

__device__ __forceinline__ uint32_t smem_u32(const void* p) {
    uint32_t a;
    asm("{ .reg .u64 t; cvta.to.shared.u64 t, %1; cvt.u32.u64 %0, t; }"
        : "=r"(a) : "l"(p));
    return a;
}

__device__ __forceinline__ void ldsm4(uint32_t& r0, uint32_t& r1, uint32_t& r2,
                                      uint32_t& r3, uint32_t addr) {
    asm volatile("ldmatrix.sync.aligned.m8n8.x4.shared.b16 {%0,%1,%2,%3}, [%4];"
                 : "=r"(r0), "=r"(r1), "=r"(r2), "=r"(r3) : "r"(addr));
}

__device__ __forceinline__ void mma16816(float& c0, float& c1, float& c2, float& c3,
                                         uint32_t a0, uint32_t a1, uint32_t a2,
                                         uint32_t a3, uint32_t b0, uint32_t b1) {
    asm volatile(
        "mma.sync.aligned.m16n8k16.row.col.f32.bf16.bf16.f32 "
        "{%0,%1,%2,%3}, {%4,%5,%6,%7}, {%8,%9}, {%0,%1,%2,%3};"
        : "+f"(c0), "+f"(c1), "+f"(c2), "+f"(c3)
        : "r"(a0), "r"(a1), "r"(a2), "r"(a3), "r"(b0), "r"(b1));
}

// fp32 pair -> bf16x2 hi (round-nearest) + bf16x2 lo (residual)
__device__ __forceinline__ void cvt_pair(float x0, float x1, uint32_t& hi, uint32_t& lo) {
    asm("cvt.rn.bf16x2.f32 %0, %1, %2;" : "=r"(hi) : "f"(x1), "f"(x0));
    float h0 = __uint_as_float(hi << 16);
    float h1 = __uint_as_float(hi & 0xFFFF0000u);
    float r0 = x0 - h0, r1 = x1 - h1;
    asm("cvt.rn.bf16x2.f32 %0, %1, %2;" : "=r"(lo) : "f"(r1), "f"(r0));
}

// Convert one chunk (K=64) of A (128 rows) and W (256 rows) into SMEM stage.
__device__ __forceinline__ void convert_chunk(const float* __restrict__ Abase,
                                              const float* __restrict__ Wbase,
                                              char* stage, int tid) {
    // A: 128 rows x 16 float4
#pragma unroll
    for (int j = 0; j < 8; j++) {
        int t = tid + j * 256;
        int r = t >> 4, c4 = t & 15;
        float4 v = *(const float4*)(Abase + (size_t)r * KTOT + c4 * 4);
        uint32_t h0, l0, h1, l1;
        cvt_pair(v.x, v.y, h0, l0);
        cvt_pair(v.z, v.w, h1, l1);
        uint32_t off = SWZ((uint32_t)(r * 128 + c4 * 8));
        *(uint2*)(stage + OFF_AHI + off) = make_uint2(h0, h1);
        *(uint2*)(stage + OFF_ALO + off) = make_uint2(l0, l1);
    }
    // B: 256 rows x 16 float4
#pragma unroll
    for (int j = 0; j < 16; j++) {
        int t = tid + j * 256;
        int r = t >> 4, c4 = t & 15;
        float4 v = *(const float4*)(Wbase + (size_t)r * KTOT + c4 * 4);
        uint32_t h0, l0, h1, l1;
        cvt_pair(v.x, v.y, h0, l0);
        cvt_pair(v.z, v.w, h1, l1);
        uint32_t off = SWZ((uint32_t)(r * 128 + c4 * 8));
        *(uint2*)(stage + OFF_BHI + off) = make_uint2(h0, h1);
        *(uint2*)(stage + OFF_BLO + off) = make_uint2(l0, l1);
    }
}

__global__ void __launch_bounds__(256, 1)
gemm_kernel(const float* __restrict__ A, const float* __restrict__ W) {
    extern __shared__ char smem[];
    uint32_t sb = smem_u32(smem);
    int tid = threadIdx.x;
    int wid = tid >> 5;
    int lane = tid & 31;

    int m0 = blockIdx.x * TM;
    int n0 = blockIdx.y * TN;
    int k0 = blockIdx.z * KLEN;

    // warp tile: 64 (M) x 64 (N)
    int wr = wid & 1;        // 0..1
    int wc = wid >> 1;       // 0..3

    // Per-thread ldmatrix row bytes (fixed per warp position)
    // A frag rows: wr*64 + mt*16 + (lane&15); col chunk: ks*2 + (lane>>4)
    uint32_t a_row[4], b_row[4];
#pragma unroll
    for (int mt = 0; mt < 4; mt++)
        a_row[mt] = (uint32_t)((wr * 64 + mt * 16 + (lane & 15)) * 128);
    // B frag rows (x4 covers 2 n-tiles): wc*64 + ntp*16 + (lane&7) + ((lane&16)>>1)
    // col chunk: ks*2 + ((lane>>3)&1)
#pragma unroll
    for (int ntp = 0; ntp < 4; ntp++)
        b_row[ntp] = (uint32_t)((wc * 64 + ntp * 16 + (lane & 7) + ((lane & 16) >> 1)) * 128);
    uint32_t a_csel = (uint32_t)((lane >> 4) * 16);        // 0 or 16
    uint32_t b_csel = (uint32_t)(((lane >> 3) & 1) * 16);  // 0 or 16

    float acc[4][8][4];
#pragma unroll
    for (int mt = 0; mt < 4; mt++)
#pragma unroll
        for (int nt = 0; nt < 8; nt++)
#pragma unroll
            for (int r = 0; r < 4; r++) acc[mt][nt][r] = 0.0f;

    const float* Abase = A + (size_t)m0 * KTOT + k0;
    const float* Wbase = W + (size_t)n0 * KTOT + k0;

    // Prologue: chunk 0 into stage 0
    convert_chunk(Abase, Wbase, smem, tid);

    for (int i = 0; i < NCHUNK; i++) {
        __syncthreads();
        int b = i & 1;
        // Prefetch-convert next chunk into other stage (LDGs issue early)
        if (i + 1 < NCHUNK)
            convert_chunk(Abase + (i + 1) * CHUNK, Wbase + (i + 1) * CHUNK,
                          smem + (b ^ 1) * STAGE_BYTES, tid);

        uint32_t stg = sb + (uint32_t)(b * STAGE_BYTES);

#pragma unroll
        for (int ks = 0; ks < 4; ks++) {
            uint32_t acsel = (uint32_t)(ks * 32) + a_csel;
            uint32_t bcsel = (uint32_t)(ks * 32) + b_csel;
            uint32_t ah[4][4], bh[4][4], xl[4][4];

            // load A-hi, B-hi
#pragma unroll
            for (int mt = 0; mt < 4; mt++)
                ldsm4(ah[mt][0], ah[mt][1], ah[mt][2], ah[mt][3],
                      stg + OFF_AHI + SWZ(a_row[mt] + acsel));
#pragma unroll
            for (int p = 0; p < 4; p++)
                ldsm4(bh[p][0], bh[p][1], bh[p][2], bh[p][3],
                      stg + OFF_BHI + SWZ(b_row[p] + bcsel));

            // term 0: ah * bh
#pragma unroll
            for (int mt = 0; mt < 4; mt++)
#pragma unroll
                for (int nt = 0; nt < 8; nt++)
                    mma16816(acc[mt][nt][0], acc[mt][nt][1], acc[mt][nt][2],
                             acc[mt][nt][3], ah[mt][0], ah[mt][1], ah[mt][2],
                             ah[mt][3], bh[nt >> 1][(nt & 1) * 2],
                             bh[nt >> 1][(nt & 1) * 2 + 1]);

            // term 1: al * bh
#pragma unroll
            for (int mt = 0; mt < 4; mt++)
                ldsm4(xl[mt][0], xl[mt][1], xl[mt][2], xl[mt][3],
                      stg + OFF_ALO + SWZ(a_row[mt] + acsel));
#pragma unroll
            for (int mt = 0; mt < 4; mt++)
#pragma unroll
                for (int nt = 0; nt < 8; nt++)
                    mma16816(acc[mt][nt][0], acc[mt][nt][1], acc[mt][nt][2],
                             acc[mt][nt][3], xl[mt][0], xl[mt][1], xl[mt][2],
                             xl[mt][3], bh[nt >> 1][(nt & 1) * 2],
                             bh[nt >> 1][(nt & 1) * 2 + 1]);

            // term 2: ah * bl
#pragma unroll
            for (int p = 0; p < 4; p++)
                ldsm4(xl[p][0], xl[p][1], xl[p][2], xl[p][3],
                      stg + OFF_BLO + SWZ(b_row[p] + bcsel));
#pragma unroll
            for (int mt = 0; mt < 4; mt++)
#pragma unroll
                for (int nt = 0; nt < 8; nt++)
                    mma16816(acc[mt][nt][0], acc[mt][nt][1], acc[mt][nt][2],
                             acc[mt][nt][3], ah[mt][0], ah[mt][1], ah[mt][2],
                             ah[mt][3], xl[nt >> 1][(nt & 1) * 2],
                             xl[nt >> 1][(nt & 1) * 2 + 1]);
        }
    }

    // Epilogue: write partials. C frag: c0,c1 at (row=lane>>2, col=2*(lane&3)), c2,c3 at row+8
    {
        float* part = g_part[blockIdx.z];
        int mbase = m0 + wr * 64;
        int nbase = n0 + wc * 64 + 2 * (lane & 3);
        int rowi = lane >> 2;
#pragma unroll
        for (int mt = 0; mt < 4; mt++) {
#pragma unroll
            for (int nt = 0; nt < 8; nt++) {
                int m = mbase + mt * 16 + rowi;
                int n = nbase + nt * 8;
                *(float2*)&part[(size_t)m * COUT + n] =
                    make_float2(acc[mt][nt][0], acc[mt][nt][1]);
                *(float2*)&part[(size_t)(m + 8) * COUT + n] =
                    make_float2(acc[mt][nt][2], acc[mt][nt][3]);
            }
        }
    }
}

// ---------------- deterministic split-K reduction ----------------
__global__ void __launch_bounds__(256)
reduce_kernel(float* __restrict__ out) {
    int idx = blockIdx.x * blockDim.x + threadIdx.x;  // float4 index, 65536 total
    float4 acc = ((const float4*)g_part[0])[idx];
#pragma unroll
    for (int s = 1; s < NSPLIT; s++) {
        float4 v = ((const float4*)g_part[s])[idx];
        acc.x += v.x; acc.y += v.y; acc.z += v.z; acc.w += v.w;
    }
    ((float4*)out)[idx] = acc;
}

extern "C" void kernel_launch(void* const* d_in, const int* in_sizes, int n_in,
                              void* d_out, int out_size) {
    const float* A = (const float*)d_in[0];   // curr_input [256,1024,16]
    const float* W = (const float*)d_in[1];   // weight     [1024,1024,16]
    float* out = (float*)d_out;               // [256,1024]

    cudaFuncSetAttribute(gemm_kernel, cudaFuncAttributeMaxDynamicSharedMemorySize,
                         SMEM_TOTAL);

    dim3 grid(BATCH / TM, COUT / TN, NSPLIT);  // (2, 4, 16) = 128 CTAs
    gemm_kernel<<<grid, 256, SMEM_TOTAL>>>(A, W);
    reduce_kernel<<<(BATCH * COUT / 4) / 256, 256>>>(out);
}

// round 4
// speedup vs baseline: 1.1605x; 1.1605x over previous
#include <cuda_runtime.h>
#include <cuda_bf16.h>
#include <cstdint>
#include <cstddef>

// out[b,o] = sum_kk A[b,kk]*W[o,kk]; A [256x16384] fp32, W [1024x16384] fp32.
// bf16 hi/lo split (3 HMMA terms), tile 128x256, split-K=16.
// R4: cp.async fp32 -> SMEM raw (dbuf), convert SMEM->SMEM bf16 (dbuf), ldsm+HMMA.

#define BATCH   256
#define COUT    1024
#define KTOT    16384
#define TM      128
#define TN      256
#define NSPLIT  16
#define KLEN    (KTOT / NSPLIT)   // 1024
#define CHUNK   32
#define NCHUNK  (KLEN / CHUNK)    // 32

__device__ float g_part[NSPLIT][BATCH * COUT];

// ---- SMEM layout ----
// raw fp32 stage s (2): A 128x32 fp32 (16K) + B 256x32 fp32 (32K) = 48K
// bf16 stage s (2): Ahi 8K | Alo 8K | Bhi 16K | Blo 16K = 48K
#define RAW_STAGE 49152
#define RAW_A(s)  ((s) * RAW_STAGE)
#define RAW_B(s)  ((s) * RAW_STAGE + 16384)
#define BF_BASE   98304
#define BF_STAGE  49152
#define BF_AHI(s) (BF_BASE + (s) * BF_STAGE)
#define BF_ALO(s) (BF_AHI(s) + 8192)
#define BF_BHI(s) (BF_AHI(s) + 16384)
#define BF_BLO(s) (BF_AHI(s) + 32768)
#define SMEM_TOTAL 196608

// 64B-row swizzle (Swizzle<2,4,3>): bits[5:4] ^= bits[8:7]
#define SWZ64(o) ((o) ^ (((o) >> 3) & 0x30))

__device__ __forceinline__ uint32_t smem_u32(const void* p) {
    uint32_t a;
    asm("{ .reg .u64 t; cvta.to.shared.u64 t, %1; cvt.u32.u64 %0, t; }"
        : "=r"(a) : "l"(p));
    return a;
}

__device__ __forceinline__ void cpa16(uint32_t dst, const void* src) {
    asm volatile("cp.async.cg.shared.global [%0], [%1], 16;"
                 :: "r"(dst), "l"(src) : "memory");
}
#define CP_COMMIT() asm volatile("cp.async.commit_group;" ::: "memory")
#define CP_WAIT1()  asm volatile("cp.async.wait_group 1;" ::: "memory")

__device__ __forceinline__ void ldsm4(uint32_t& r0, uint32_t& r1, uint32_t& r2,
                                      uint32_t& r3, uint32_t addr) {
    asm volatile("ldmatrix.sync.aligned.m8n8.x4.shared.b16 {%0,%1,%2,%3}, [%4];"
                 : "=r"(r0), "=r"(r1), "=r"(r2), "=r"(r3) : "r"(addr));
}

__device__ __forceinline__ void mma16816(float& c0, float& c1, float& c2, float& c3,
                                         uint32_t a0, uint32_t a1, uint32_t a2,
                                         uint32_t a3, uint32_t b0, uint32_t b1) {
    asm volatile(
        "mma.sync.aligned.m16n8k16.row.col.f32.bf16.bf16.f32 "
        "{%0,%1,%2,%3}, {%4,%5,%6,%7}, {%8,%9}, {%0,%1,%2,%3};"
        : "+f"(c0), "+f"(c1), "+f"(c2), "+f"(c3)
        : "r"(a0), "r"(a1), "r"(a2), "r"(a3), "r"(b0), "r"(b1));
}

// fp32 pair -> bf16x2 hi (RN) + bf16x2 lo (residual, RN)
__device__ __forceinline__ void cvt_pair(float x0, float x1, uint32_t& hi, uint32_t& lo) {
    asm("cvt.rn.bf16x2.f32 %0, %1, %2;" : "=r"(hi) : "f"(x1), "f"(x0));
    float h0 = __uint_as_float(hi << 16);
    float h1 = __uint_as_float(hi & 0xFFFF0000u);
    float r0 = x0 - h0, r1 = x1 - h1;
    asm("cvt.rn.bf16x2.f32 %0, %1, %2;" : "=r"(lo) : "f"(r1), "f"(r0));
}

// Issue cp.asyncs for chunk ich into raw stage s. Thread t owns rows t>>3 + 32j, float4 t&7.
__device__ __forceinline__ void load_raw(const float* __restrict__ Abase,
                                         const float* __restrict__ Wbase,
                                         uint32_t sb, int s, int ich, int tid) {
    uint32_t ra = sb + (uint32_t)RAW_A(s);
    uint32_t rb = sb + (uint32_t)RAW_B(s);
    int r0 = tid >> 3, c4 = tid & 7;
    const float* Ap = Abase + (size_t)ich * CHUNK + (size_t)r0 * KTOT + c4 * 4;
#pragma unroll
    for (int j = 0; j < 4; j++)
        cpa16(ra + (uint32_t)((r0 + 32 * j) * 128 + c4 * 16),
              Ap + (size_t)(32 * j) * KTOT);
    const float* Wp = Wbase + (size_t)ich * CHUNK + (size_t)r0 * KTOT + c4 * 4;
#pragma unroll
    for (int j = 0; j < 8; j++)
        cpa16(rb + (uint32_t)((r0 + 32 * j) * 128 + c4 * 16),
              Wp + (size_t)(32 * j) * KTOT);
}

// Convert raw stage s -> bf16 stage s. Same per-thread ownership as load_raw:
// each thread only touches data it cp.async'd itself (wait_group suffices).
__device__ __forceinline__ void convert_stage(char* smem, int s, int tid) {
    int r0 = tid >> 3, c4 = tid & 7;
    const float4* rawA = (const float4*)(smem + RAW_A(s));
#pragma unroll
    for (int j = 0; j < 4; j++) {
        int r = r0 + 32 * j;
        float4 v = rawA[r * 8 + c4];
        uint32_t h0, l0, h1, l1;
        cvt_pair(v.x, v.y, h0, l0);
        cvt_pair(v.z, v.w, h1, l1);
        uint32_t off = SWZ64((uint32_t)(r * 64 + c4 * 8));
        *(uint2*)(smem + BF_AHI(s) + off) = make_uint2(h0, h1);
        *(uint2*)(smem + BF_ALO(s) + off) = make_uint2(l0, l1);
    }
    const float4* rawB = (const float4*)(smem + RAW_B(s));
#pragma unroll
    for (int j = 0; j < 8; j++) {
        int r = r0 + 32 * j;
        float4 v = rawB[r * 8 + c4];
        uint32_t h0, l0, h1, l1;
        cvt_pair(v.x, v.y, h0, l0);
        cvt_pair(v.z, v.w, h1, l1);
        uint32_t off = SWZ64((uint32_t)(r * 64 + c4 * 8));
        *(uint2*)(smem + BF_BHI(s) + off) = make_uint2(h0, h1);
        *(uint2*)(smem + BF_BLO(s) + off) = make_uint2(l0, l1);
    }
}

__global__ void __launch_bounds__(256, 1)
gemm_kernel(const float* __restrict__ A, const float* __restrict__ W) {
    extern __shared__ char smem[];
    uint32_t sb = smem_u32(smem);
    int tid = threadIdx.x;
    int wid = tid >> 5;
    int lane = tid & 31;

    int m0 = blockIdx.x * TM;
    int n0 = blockIdx.y * TN;
    int k0 = blockIdx.z * KLEN;

    int wr = wid & 1;        // warp tile 64x64: row half
    int wc = wid >> 1;       // col quarter

    // ldmatrix byte-row bases (64B rows)
    uint32_t a_row[4], b_row[4];
#pragma unroll
    for (int mt = 0; mt < 4; mt++)
        a_row[mt] = (uint32_t)((wr * 64 + mt * 16 + (lane & 15)) * 64);
#pragma unroll
    for (int p = 0; p < 4; p++)
        b_row[p] = (uint32_t)((wc * 64 + p * 16 + (lane & 7) + ((lane & 16) >> 1)) * 64);
    uint32_t a_csel = (uint32_t)((lane >> 4) * 16);
    uint32_t b_csel = (uint32_t)(((lane >> 3) & 1) * 16);

    float acc[4][8][4];
#pragma unroll
    for (int mt = 0; mt < 4; mt++)
#pragma unroll
        for (int nt = 0; nt < 8; nt++)
#pragma unroll
            for (int r = 0; r < 4; r++) acc[mt][nt][r] = 0.0f;

    const float* Abase = A + (size_t)m0 * KTOT + k0;
    const float* Wbase = W + (size_t)n0 * KTOT + k0;

    // Prologue: prefetch chunks 0,1; convert chunk 0.
    load_raw(Abase, Wbase, sb, 0, 0, tid);
    CP_COMMIT();
    load_raw(Abase, Wbase, sb, 1, 1, tid);
    CP_COMMIT();
    CP_WAIT1();               // chunk 0 raw ready (own thread's data)
    convert_stage(smem, 0, tid);
    __syncthreads();          // bf16 stage 0 visible to all warps

    for (int i = 0; i < NCHUNK; i++) {
        int s = i & 1;
        // Prefetch chunk i+2 into raw[s] (its old contents, chunk i, were
        // converted by this same thread in the previous iteration).
        if (i + 2 < NCHUNK) load_raw(Abase, Wbase, sb, s, i + 2, tid);
        CP_COMMIT();

        // --- MMA on bf16 stage s (chunk i) ---
        uint32_t bfa_hi = sb + (uint32_t)BF_AHI(s);
        uint32_t bfa_lo = sb + (uint32_t)BF_ALO(s);
        uint32_t bfb_hi = sb + (uint32_t)BF_BHI(s);
        uint32_t bfb_lo = sb + (uint32_t)BF_BLO(s);

#pragma unroll
        for (int ks = 0; ks < 2; ks++) {
            uint32_t acsel = (uint32_t)(ks * 32) + a_csel;
            uint32_t bcsel = (uint32_t)(ks * 32) + b_csel;
            uint32_t ah[4][4], bh[4][4], xl[4][4];

#pragma unroll
            for (int mt = 0; mt < 4; mt++)
                ldsm4(ah[mt][0], ah[mt][1], ah[mt][2], ah[mt][3],
                      bfa_hi + SWZ64(a_row[mt] + acsel));
#pragma unroll
            for (int p = 0; p < 4; p++)
                ldsm4(bh[p][0], bh[p][1], bh[p][2], bh[p][3],
                      bfb_hi + SWZ64(b_row[p] + bcsel));

            // term 0: ah*bh
#pragma unroll
            for (int mt = 0; mt < 4; mt++)
#pragma unroll
                for (int nt = 0; nt < 8; nt++)
                    mma16816(acc[mt][nt][0], acc[mt][nt][1], acc[mt][nt][2],
                             acc[mt][nt][3], ah[mt][0], ah[mt][1], ah[mt][2],
                             ah[mt][3], bh[nt >> 1][(nt & 1) * 2],
                             bh[nt >> 1][(nt & 1) * 2 + 1]);

            // term 1: al*bh
#pragma unroll
            for (int mt = 0; mt < 4; mt++)
                ldsm4(xl[mt][0], xl[mt][1], xl[mt][2], xl[mt][3],
                      bfa_lo + SWZ64(a_row[mt] + acsel));
#pragma unroll
            for (int mt = 0; mt < 4; mt++)
#pragma unroll
                for (int nt = 0; nt < 8; nt++)
                    mma16816(acc[mt][nt][0], acc[mt][nt][1], acc[mt][nt][2],
                             acc[mt][nt][3], xl[mt][0], xl[mt][1], xl[mt][2],
                             xl[mt][3], bh[nt >> 1][(nt & 1) * 2],
                             bh[nt >> 1][(nt & 1) * 2 + 1]);

            // term 2: ah*bl
#pragma unroll
            for (int p = 0; p < 4; p++)
                ldsm4(xl[p][0], xl[p][1], xl[p][2], xl[p][3],
                      bfb_lo + SWZ64(b_row[p] + bcsel));
#pragma unroll
            for (int mt = 0; mt < 4; mt++)
#pragma unroll
                for (int nt = 0; nt < 8; nt++)
                    mma16816(acc[mt][nt][0], acc[mt][nt][1], acc[mt][nt][2],
                             acc[mt][nt][3], ah[mt][0], ah[mt][1], ah[mt][2],
                             ah[mt][3], xl[nt >> 1][(nt & 1) * 2],
                             xl[nt >> 1][(nt & 1) * 2 + 1]);
        }

        // --- convert chunk i+1 (raw arrived long ago; wait is cheap) ---
        if (i + 1 < NCHUNK) {
            CP_WAIT1();
            convert_stage(smem, (i + 1) & 1, tid);
        }
        __syncthreads();
    }

    // Epilogue: write split-K partials.
    {
        float* part = g_part[blockIdx.z];
        int mbase = m0 + wr * 64;
        int nbase = n0 + wc * 64 + 2 * (lane & 3);
        int rowi = lane >> 2;
#pragma unroll
        for (int mt = 0; mt < 4; mt++) {
#pragma unroll
            for (int nt = 0; nt < 8; nt++) {
                int m = mbase + mt * 16 + rowi;
                int n = nbase + nt * 8;
                *(float2*)&part[(size_t)m * COUT + n] =
                    make_float2(acc[mt][nt][0], acc[mt][nt][1]);
                *(float2*)&part[(size_t)(m + 8) * COUT + n] =
                    make_float2(acc[mt][nt][2], acc[mt][nt][3]);
            }
        }
    }
}

// ---------------- deterministic split-K reduction ----------------
__global__ void __launch_bounds__(256)
reduce_kernel(float* __restrict__ out) {
    int idx = blockIdx.x * blockDim.x + threadIdx.x;  // float4 index, 65536 total
    float4 acc = ((const float4*)g_part[0])[idx];
#pragma unroll
    for (int s = 1; s < NSPLIT; s++) {
        float4 v = ((const float4*)g_part[s])[idx];
        acc.x += v.x; acc.y += v.y; acc.z += v.z; acc.w += v.w;
    }
    ((float4*)out)[idx] = acc;
}

extern "C" void kernel_launch(void* const* d_in, const int* in_sizes, int n_in,
                              void* d_out, int out_size) {
    const float* A = (const float*)d_in[0];   // curr_input [256,1024,16]
    const float* W = (const float*)d_in[1];   // weight     [1024,1024,16]
    float* out = (float*)d_out;               // [256,1024]

    cudaFuncSetAttribute(gemm_kernel, cudaFuncAttributeMaxDynamicSharedMemorySize,
                         SMEM_TOTAL);

    dim3 grid(BATCH / TM, COUT / TN, NSPLIT);  // (2, 4, 16) = 128 CTAs
    gemm_kernel<<<grid, 256, SMEM_TOTAL>>>(A, W);
    reduce_kernel<<<(BATCH * COUT / 4) / 256, 256>>>(out);
}

// round 5
// speedup vs baseline: 1.4760x; 1.2719x over previous
#include <cuda_runtime.h>
#include <cuda_fp16.h>
#include <cstdint>
#include <cstddef>

// out[b,o] = sum_kk A[b,kk]*W[o,kk]; A [256x16384] fp32, W [1024x16384] fp32.
// R5: fp16 2-term split (A = ah+al, W = wh; drop a*wl ~ 2^-11), HMMA f16,
// tile 128x256, split-K=16, cp.async raw-fp32 dbuf + SMEM convert dbuf.

#define BATCH   256
#define COUT    1024
#define KTOT    16384
#define TM      128
#define TN      256
#define NSPLIT  16
#define KLEN    (KTOT / NSPLIT)   // 1024
#define CHUNK   32
#define NCHUNK  (KLEN / CHUNK)    // 32

__device__ float g_part[NSPLIT][BATCH * COUT];

// ---- SMEM layout ----
// raw fp32 stage s (2): A 128x32 (16K) + B 256x32 (32K) = 48K
// fp16 stage s (2): Ahi 8K | Alo 8K | Bhi 16K = 32K
#define RAW_STAGE 49152
#define RAW_A(s)  ((s) * RAW_STAGE)
#define RAW_B(s)  ((s) * RAW_STAGE + 16384)
#define BF_BASE   98304
#define BF_STAGE  32768
#define BF_AHI(s) (BF_BASE + (s) * BF_STAGE)
#define BF_ALO(s) (BF_AHI(s) + 8192)
#define BF_BHI(s) (BF_AHI(s) + 16384)
#define SMEM_TOTAL (BF_BASE + 2 * BF_STAGE)   // 163840

// 64B-row swizzle (Swizzle<2,4,3>): bits[5:4] ^= bits[8:7]
#define SWZ64(o) ((o) ^ (((o) >> 3) & 0x30))

__device__ __forceinline__ uint32_t smem_u32(const void* p) {
    uint32_t a;
    asm("{ .reg .u64 t; cvta.to.shared.u64 t, %1; cvt.u32.u64 %0, t; }"
        : "=r"(a) : "l"(p));
    return a;
}

__device__ __forceinline__ void cpa16(uint32_t dst, const void* src) {
    asm volatile("cp.async.cg.shared.global [%0], [%1], 16;"
                 :: "r"(dst), "l"(src) : "memory");
}
#define CP_COMMIT() asm volatile("cp.async.commit_group;" ::: "memory")
#define CP_WAIT1()  asm volatile("cp.async.wait_group 1;" ::: "memory")

__device__ __forceinline__ void ldsm4(uint32_t& r0, uint32_t& r1, uint32_t& r2,
                                      uint32_t& r3, uint32_t addr) {
    asm volatile("ldmatrix.sync.aligned.m8n8.x4.shared.b16 {%0,%1,%2,%3}, [%4];"
                 : "=r"(r0), "=r"(r1), "=r"(r2), "=r"(r3) : "r"(addr));
}

__device__ __forceinline__ void mma16816(float& c0, float& c1, float& c2, float& c3,
                                         uint32_t a0, uint32_t a1, uint32_t a2,
                                         uint32_t a3, uint32_t b0, uint32_t b1) {
    asm volatile(
        "mma.sync.aligned.m16n8k16.row.col.f32.f16.f16.f32 "
        "{%0,%1,%2,%3}, {%4,%5,%6,%7}, {%8,%9}, {%0,%1,%2,%3};"
        : "+f"(c0), "+f"(c1), "+f"(c2), "+f"(c3)
        : "r"(a0), "r"(a1), "r"(a2), "r"(a3), "r"(b0), "r"(b1));
}

// fp32 pair -> fp16x2 hi (RN) + fp16x2 lo (residual, RN)
__device__ __forceinline__ void cvt_pair_hl(float x0, float x1, uint32_t& hi, uint32_t& lo) {
    asm("cvt.rn.f16x2.f32 %0, %1, %2;" : "=r"(hi) : "f"(x1), "f"(x0));
    __half2 h2 = *reinterpret_cast<__half2*>(&hi);
    float2 hf = __half22float2(h2);
    float r0 = x0 - hf.x, r1 = x1 - hf.y;
    asm("cvt.rn.f16x2.f32 %0, %1, %2;" : "=r"(lo) : "f"(r1), "f"(r0));
}

// fp32 pair -> fp16x2 (RN), hi only
__device__ __forceinline__ uint32_t cvt_pair_h(float x0, float x1) {
    uint32_t hi;
    asm("cvt.rn.f16x2.f32 %0, %1, %2;" : "=r"(hi) : "f"(x1), "f"(x0));
    return hi;
}

// Issue cp.asyncs for chunk ich into raw stage s. Thread t owns rows t>>3 + 32j, float4 t&7.
__device__ __forceinline__ void load_raw(const float* __restrict__ Abase,
                                         const float* __restrict__ Wbase,
                                         uint32_t sb, int s, int ich, int tid) {
    uint32_t ra = sb + (uint32_t)RAW_A(s);
    uint32_t rb = sb + (uint32_t)RAW_B(s);
    int r0 = tid >> 3, c4 = tid & 7;
    const float* Ap = Abase + (size_t)ich * CHUNK + (size_t)r0 * KTOT + c4 * 4;
#pragma unroll
    for (int j = 0; j < 4; j++)
        cpa16(ra + (uint32_t)((r0 + 32 * j) * 128 + c4 * 16),
              Ap + (size_t)(32 * j) * KTOT);
    const float* Wp = Wbase + (size_t)ich * CHUNK + (size_t)r0 * KTOT + c4 * 4;
#pragma unroll
    for (int j = 0; j < 8; j++)
        cpa16(rb + (uint32_t)((r0 + 32 * j) * 128 + c4 * 16),
              Wp + (size_t)(32 * j) * KTOT);
}

// Convert raw stage s -> fp16 stage s. Each thread converts only data it cp.async'd.
__device__ __forceinline__ void convert_stage(char* smem, int s, int tid) {
    int r0 = tid >> 3, c4 = tid & 7;
    const float4* rawA = (const float4*)(smem + RAW_A(s));
#pragma unroll
    for (int j = 0; j < 4; j++) {
        int r = r0 + 32 * j;
        float4 v = rawA[r * 8 + c4];
        uint32_t h0, l0, h1, l1;
        cvt_pair_hl(v.x, v.y, h0, l0);
        cvt_pair_hl(v.z, v.w, h1, l1);
        uint32_t off = SWZ64((uint32_t)(r * 64 + c4 * 8));
        *(uint2*)(smem + BF_AHI(s) + off) = make_uint2(h0, h1);
        *(uint2*)(smem + BF_ALO(s) + off) = make_uint2(l0, l1);
    }
    const float4* rawB = (const float4*)(smem + RAW_B(s));
#pragma unroll
    for (int j = 0; j < 8; j++) {
        int r = r0 + 32 * j;
        float4 v = rawB[r * 8 + c4];
        uint32_t h0 = cvt_pair_h(v.x, v.y);
        uint32_t h1 = cvt_pair_h(v.z, v.w);
        uint32_t off = SWZ64((uint32_t)(r * 64 + c4 * 8));
        *(uint2*)(smem + BF_BHI(s) + off) = make_uint2(h0, h1);
    }
}

__global__ void __launch_bounds__(256, 1)
gemm_kernel(const float* __restrict__ A, const float* __restrict__ W) {
    extern __shared__ char smem[];
    uint32_t sb = smem_u32(smem);
    int tid = threadIdx.x;
    int wid = tid >> 5;
    int lane = tid & 31;

    int m0 = blockIdx.x * TM;
    int n0 = blockIdx.y * TN;
    int k0 = blockIdx.z * KLEN;

    int wr = wid & 1;        // warp tile 64x64: row half
    int wc = wid >> 1;       // col quarter

    uint32_t a_row[4], b_row[4];
#pragma unroll
    for (int mt = 0; mt < 4; mt++)
        a_row[mt] = (uint32_t)((wr * 64 + mt * 16 + (lane & 15)) * 64);
#pragma unroll
    for (int p = 0; p < 4; p++)
        b_row[p] = (uint32_t)((wc * 64 + p * 16 + (lane & 7) + ((lane & 16) >> 1)) * 64);
    uint32_t a_csel = (uint32_t)((lane >> 4) * 16);
    uint32_t b_csel = (uint32_t)(((lane >> 3) & 1) * 16);

    float acc[4][8][4];
#pragma unroll
    for (int mt = 0; mt < 4; mt++)
#pragma unroll
        for (int nt = 0; nt < 8; nt++)
#pragma unroll
            for (int r = 0; r < 4; r++) acc[mt][nt][r] = 0.0f;

    const float* Abase = A + (size_t)m0 * KTOT + k0;
    const float* Wbase = W + (size_t)n0 * KTOT + k0;

    // Prologue: prefetch chunks 0,1; convert chunk 0.
    load_raw(Abase, Wbase, sb, 0, 0, tid);
    CP_COMMIT();
    load_raw(Abase, Wbase, sb, 1, 1, tid);
    CP_COMMIT();
    CP_WAIT1();
    convert_stage(smem, 0, tid);
    __syncthreads();

    for (int i = 0; i < NCHUNK; i++) {
        int s = i & 1;
        if (i + 2 < NCHUNK) load_raw(Abase, Wbase, sb, s, i + 2, tid);
        CP_COMMIT();

        uint32_t bfa_hi = sb + (uint32_t)BF_AHI(s);
        uint32_t bfa_lo = sb + (uint32_t)BF_ALO(s);
        uint32_t bfb_hi = sb + (uint32_t)BF_BHI(s);

#pragma unroll
        for (int ks = 0; ks < 2; ks++) {
            uint32_t acsel = (uint32_t)(ks * 32) + a_csel;
            uint32_t bcsel = (uint32_t)(ks * 32) + b_csel;
            uint32_t ah[4][4], bh[4][4], al[4][4];

#pragma unroll
            for (int mt = 0; mt < 4; mt++)
                ldsm4(ah[mt][0], ah[mt][1], ah[mt][2], ah[mt][3],
                      bfa_hi + SWZ64(a_row[mt] + acsel));
#pragma unroll
            for (int p = 0; p < 4; p++)
                ldsm4(bh[p][0], bh[p][1], bh[p][2], bh[p][3],
                      bfb_hi + SWZ64(b_row[p] + bcsel));

            // term 0: ah * wh
#pragma unroll
            for (int mt = 0; mt < 4; mt++)
#pragma unroll
                for (int nt = 0; nt < 8; nt++)
                    mma16816(acc[mt][nt][0], acc[mt][nt][1], acc[mt][nt][2],
                             acc[mt][nt][3], ah[mt][0], ah[mt][1], ah[mt][2],
                             ah[mt][3], bh[nt >> 1][(nt & 1) * 2],
                             bh[nt >> 1][(nt & 1) * 2 + 1]);

            // term 1: al * wh
#pragma unroll
            for (int mt = 0; mt < 4; mt++)
                ldsm4(al[mt][0], al[mt][1], al[mt][2], al[mt][3],
                      bfa_lo + SWZ64(a_row[mt] + acsel));
#pragma unroll
            for (int mt = 0; mt < 4; mt++)
#pragma unroll
                for (int nt = 0; nt < 8; nt++)
                    mma16816(acc[mt][nt][0], acc[mt][nt][1], acc[mt][nt][2],
                             acc[mt][nt][3], al[mt][0], al[mt][1], al[mt][2],
                             al[mt][3], bh[nt >> 1][(nt & 1) * 2],
                             bh[nt >> 1][(nt & 1) * 2 + 1]);
        }

        if (i + 1 < NCHUNK) {
            CP_WAIT1();
            convert_stage(smem, (i + 1) & 1, tid);
        }
        __syncthreads();
    }

    // Epilogue: write split-K partials.
    {
        float* part = g_part[blockIdx.z];
        int mbase = m0 + wr * 64;
        int nbase = n0 + wc * 64 + 2 * (lane & 3);
        int rowi = lane >> 2;
#pragma unroll
        for (int mt = 0; mt < 4; mt++) {
#pragma unroll
            for (int nt = 0; nt < 8; nt++) {
                int m = mbase + mt * 16 + rowi;
                int n = nbase + nt * 8;
                *(float2*)&part[(size_t)m * COUT + n] =
                    make_float2(acc[mt][nt][0], acc[mt][nt][1]);
                *(float2*)&part[(size_t)(m + 8) * COUT + n] =
                    make_float2(acc[mt][nt][2], acc[mt][nt][3]);
            }
        }
    }
}

// ---------------- deterministic split-K reduction ----------------
__global__ void __launch_bounds__(256)
reduce_kernel(float* __restrict__ out) {
    int idx = blockIdx.x * blockDim.x + threadIdx.x;  // float4 index, 65536 total
    float4 acc = ((const float4*)g_part[0])[idx];
#pragma unroll
    for (int s = 1; s < NSPLIT; s++) {
        float4 v = ((const float4*)g_part[s])[idx];
        acc.x += v.x; acc.y += v.y; acc.z += v.z; acc.w += v.w;
    }
    ((float4*)out)[idx] = acc;
}

extern "C" void kernel_launch(void* const* d_in, const int* in_sizes, int n_in,
                              void* d_out, int out_size) {
    const float* A = (const float*)d_in[0];   // curr_input [256,1024,16]
    const float* W = (const float*)d_in[1];   // weight     [1024,1024,16]
    float* out = (float*)d_out;               // [256,1024]

    cudaFuncSetAttribute(gemm_kernel, cudaFuncAttributeMaxDynamicSharedMemorySize,
                         SMEM_TOTAL);

    dim3 grid(BATCH / TM, COUT / TN, NSPLIT);  // (2, 4, 16) = 128 CTAs
    gemm_kernel<<<grid, 256, SMEM_TOTAL>>>(A, W);
    reduce_kernel<<<(BATCH * COUT / 4) / 256, 256>>>(out);
}

// round 7
// speedup vs baseline: 2.0232x; 1.3707x over previous
#include <cuda_runtime.h>
#include <cuda_fp16.h>
#include <cstdint>
#include <cstddef>

// out[b,o] = sum_kk A[b,kk]*W[o,kk]; A [256x16384] fp32, W [1024x16384] fp32.
// R6: plain fp16 single-term HMMA (rel_err ~3e-4 < 1e-3), tile 128x256,
// split-K=16, cp.async raw-fp32 dbuf + SMEM convert dbuf, float2 reduce.

#define BATCH   256
#define COUT    1024
#define KTOT    16384
#define TM      128
#define TN      256
#define NSPLIT  16
#define KLEN    (KTOT / NSPLIT)   // 1024
#define CHUNK   32
#define NCHUNK  (KLEN / CHUNK)    // 32

__device__ float g_part[NSPLIT][BATCH * COUT];

// ---- SMEM layout ----
// raw fp32 stage s (2): A 128x32 (16K) + B 256x32 (32K) = 48K
// fp16 stage s (2): Ah 8K | Bh 16K = 24K
#define RAW_STAGE 49152
#define RAW_A(s)  ((s) * RAW_STAGE)
#define RAW_B(s)  ((s) * RAW_STAGE + 16384)
#define BF_BASE   98304
#define BF_STAGE  24576
#define BF_AH(s)  (BF_BASE + (s) * BF_STAGE)
#define BF_BH(s)  (BF_AH(s) + 8192)
#define SMEM_TOTAL (BF_BASE + 2 * BF_STAGE)   // 147456

// 64B-row swizzle (Swizzle<2,4,3>): bits[5:4] ^= bits[8:7]
#define SWZ64(o) ((o) ^ (((o) >> 3) & 0x30))

__device__ __forceinline__ uint32_t smem_u32(const void* p) {
    uint32_t a;
    asm("{ .reg .u64 t; cvta.to.shared.u64 t, %1; cvt.u32.u64 %0, t; }"
        : "=r"(a) : "l"(p));
    return a;
}

__device__ __forceinline__ void cpa16(uint32_t dst, const void* src) {
    asm volatile("cp.async.cg.shared.global [%0], [%1], 16;"
                 :: "r"(dst), "l"(src) : "memory");
}
#define CP_COMMIT() asm volatile("cp.async.commit_group;" ::: "memory")
#define CP_WAIT1()  asm volatile("cp.async.wait_group 1;" ::: "memory")

__device__ __forceinline__ void ldsm4(uint32_t& r0, uint32_t& r1, uint32_t& r2,
                                      uint32_t& r3, uint32_t addr) {
    asm volatile("ldmatrix.sync.aligned.m8n8.x4.shared.b16 {%0,%1,%2,%3}, [%4];"
                 : "=r"(r0), "=r"(r1), "=r"(r2), "=r"(r3) : "r"(addr));
}

__device__ __forceinline__ void mma16816(float& c0, float& c1, float& c2, float& c3,
                                         uint32_t a0, uint32_t a1, uint32_t a2,
                                         uint32_t a3, uint32_t b0, uint32_t b1) {
    asm volatile(
        "mma.sync.aligned.m16n8k16.row.col.f32.f16.f16.f32 "
        "{%0,%1,%2,%3}, {%4,%5,%6,%7}, {%8,%9}, {%0,%1,%2,%3};"
        : "+f"(c0), "+f"(c1), "+f"(c2), "+f"(c3)
        : "r"(a0), "r"(a1), "r"(a2), "r"(a3), "r"(b0), "r"(b1));
}

// fp32 pair -> fp16x2 (RN)
__device__ __forceinline__ uint32_t cvt_pair_h(float x0, float x1) {
    uint32_t hi;
    asm("cvt.rn.f16x2.f32 %0, %1, %2;" : "=r"(hi) : "f"(x1), "f"(x0));
    return hi;
}

// Issue cp.asyncs for chunk ich into raw stage s. Thread t owns rows t>>3 + 32j, float4 t&7.
__device__ __forceinline__ void load_raw(const float* __restrict__ Abase,
                                         const float* __restrict__ Wbase,
                                         uint32_t sb, int s, int ich, int tid) {
    uint32_t ra = sb + (uint32_t)RAW_A(s);
    uint32_t rb = sb + (uint32_t)RAW_B(s);
    int r0 = tid >> 3, c4 = tid & 7;
    const float* Ap = Abase + (size_t)ich * CHUNK + (size_t)r0 * KTOT + c4 * 4;
#pragma unroll
    for (int j = 0; j < 4; j++)
        cpa16(ra + (uint32_t)((r0 + 32 * j) * 128 + c4 * 16),
              Ap + (size_t)(32 * j) * KTOT);
    const float* Wp = Wbase + (size_t)ich * CHUNK + (size_t)r0 * KTOT + c4 * 4;
#pragma unroll
    for (int j = 0; j < 8; j++)
        cpa16(rb + (uint32_t)((r0 + 32 * j) * 128 + c4 * 16),
              Wp + (size_t)(32 * j) * KTOT);
}

// Convert raw stage s -> fp16 stage s. Each thread converts only data it cp.async'd.
__device__ __forceinline__ void convert_stage(char* smem, int s, int tid) {
    int r0 = tid >> 3, c4 = tid & 7;
    const float4* rawA = (const float4*)(smem + RAW_A(s));
#pragma unroll
    for (int j = 0; j < 4; j++) {
        int r = r0 + 32 * j;
        float4 v = rawA[r * 8 + c4];
        uint32_t h0 = cvt_pair_h(v.x, v.y);
        uint32_t h1 = cvt_pair_h(v.z, v.w);
        uint32_t off = SWZ64((uint32_t)(r * 64 + c4 * 8));
        *(uint2*)(smem + BF_AH(s) + off) = make_uint2(h0, h1);
    }
    const float4* rawB = (const float4*)(smem + RAW_B(s));
#pragma unroll
    for (int j = 0; j < 8; j++) {
        int r = r0 + 32 * j;
        float4 v = rawB[r * 8 + c4];
        uint32_t h0 = cvt_pair_h(v.x, v.y);
        uint32_t h1 = cvt_pair_h(v.z, v.w);
        uint32_t off = SWZ64((uint32_t)(r * 64 + c4 * 8));
        *(uint2*)(smem + BF_BH(s) + off) = make_uint2(h0, h1);
    }
}

__global__ void __launch_bounds__(256, 1)
gemm_kernel(const float* __restrict__ A, const float* __restrict__ W) {
    extern __shared__ char smem[];
    uint32_t sb = smem_u32(smem);
    int tid = threadIdx.x;
    int wid = tid >> 5;
    int lane = tid & 31;

    int m0 = blockIdx.x * TM;
    int n0 = blockIdx.y * TN;
    int k0 = blockIdx.z * KLEN;

    int wr = wid & 1;        // warp tile 64x64: row half
    int wc = wid >> 1;       // col quarter

    uint32_t a_row[4], b_row[4];
#pragma unroll
    for (int mt = 0; mt < 4; mt++)
        a_row[mt] = (uint32_t)((wr * 64 + mt * 16 + (lane & 15)) * 64);
#pragma unroll
    for (int p = 0; p < 4; p++)
        b_row[p] = (uint32_t)((wc * 64 + p * 16 + (lane & 7) + ((lane & 16) >> 1)) * 64);
    uint32_t a_csel = (uint32_t)((lane >> 4) * 16);
    uint32_t b_csel = (uint32_t)(((lane >> 3) & 1) * 16);

    float acc[4][8][4];
#pragma unroll
    for (int mt = 0; mt < 4; mt++)
#pragma unroll
        for (int nt = 0; nt < 8; nt++)
#pragma unroll
            for (int r = 0; r < 4; r++) acc[mt][nt][r] = 0.0f;

    const float* Abase = A + (size_t)m0 * KTOT + k0;
    const float* Wbase = W + (size_t)n0 * KTOT + k0;

    // Prologue: prefetch chunks 0,1; convert chunk 0.
    load_raw(Abase, Wbase, sb, 0, 0, tid);
    CP_COMMIT();
    load_raw(Abase, Wbase, sb, 1, 1, tid);
    CP_COMMIT();
    CP_WAIT1();
    convert_stage(smem, 0, tid);
    __syncthreads();

    for (int i = 0; i < NCHUNK; i++) {
        int s = i & 1;
        if (i + 2 < NCHUNK) load_raw(Abase, Wbase, sb, s, i + 2, tid);
        CP_COMMIT();

        uint32_t bfa = sb + (uint32_t)BF_AH(s);
        uint32_t bfb = sb + (uint32_t)BF_BH(s);

#pragma unroll
        for (int ks = 0; ks < 2; ks++) {
            uint32_t acsel = (uint32_t)(ks * 32) + a_csel;
            uint32_t bcsel = (uint32_t)(ks * 32) + b_csel;
            uint32_t ah[4][4], bh[4][4];

#pragma unroll
            for (int mt = 0; mt < 4; mt++)
                ldsm4(ah[mt][0], ah[mt][1], ah[mt][2], ah[mt][3],
                      bfa + SWZ64(a_row[mt] + acsel));
#pragma unroll
            for (int p = 0; p < 4; p++)
                ldsm4(bh[p][0], bh[p][1], bh[p][2], bh[p][3],
                      bfb + SWZ64(b_row[p] + bcsel));

#pragma unroll
            for (int mt = 0; mt < 4; mt++)
#pragma unroll
                for (int nt = 0; nt < 8; nt++)
                    mma16816(acc[mt][nt][0], acc[mt][nt][1], acc[mt][nt][2],
                             acc[mt][nt][3], ah[mt][0], ah[mt][1], ah[mt][2],
                             ah[mt][3], bh[nt >> 1][(nt & 1) * 2],
                             bh[nt >> 1][(nt & 1) * 2 + 1]);
        }

        if (i + 1 < NCHUNK) {
            CP_WAIT1();
            convert_stage(smem, (i + 1) & 1, tid);
        }
        __syncthreads();
    }

    // Epilogue: write split-K partials.
    {
        float* part = g_part[blockIdx.z];
        int mbase = m0 + wr * 64;
        int nbase = n0 + wc * 64 + 2 * (lane & 3);
        int rowi = lane >> 2;
#pragma unroll
        for (int mt = 0; mt < 4; mt++) {
#pragma unroll
            for (int nt = 0; nt < 8; nt++) {
                int m = mbase + mt * 16 + rowi;
                int n = nbase + nt * 8;
                *(float2*)&part[(size_t)m * COUT + n] =
                    make_float2(acc[mt][nt][0], acc[mt][nt][1]);
                *(float2*)&part[(size_t)(m + 8) * COUT + n] =
                    make_float2(acc[mt][nt][2], acc[mt][nt][3]);
            }
        }
    }
}

// ---------------- deterministic split-K reduction (float2 granularity) ----------------
__global__ void __launch_bounds__(256)
reduce_kernel(float* __restrict__ out) {
    int idx = blockIdx.x * blockDim.x + threadIdx.x;  // float2 index, 131072 total
    float2 acc = ((const float2*)g_part[0])[idx];
#pragma unroll
    for (int s = 1; s < NSPLIT; s++) {
        float2 v = ((const float2*)g_part[s])[idx];
        acc.x += v.x; acc.y += v.y;
    }
    ((float2*)out)[idx] = acc;
}

extern "C" void kernel_launch(void* const* d_in, const int* in_sizes, int n_in,
                              void* d_out, int out_size) {
    const float* A = (const float*)d_in[0];   // curr_input [256,1024,16]
    const float* W = (const float*)d_in[1];   // weight     [1024,1024,16]
    float* out = (float*)d_out;               // [256,1024]

    cudaFuncSetAttribute(gemm_kernel, cudaFuncAttributeMaxDynamicSharedMemorySize,
                         SMEM_TOTAL);

    dim3 grid(BATCH / TM, COUT / TN, NSPLIT);  // (2, 4, 16) = 128 CTAs
    gemm_kernel<<<grid, 256, SMEM_TOTAL>>>(A, W);
    reduce_kernel<<<(BATCH * COUT / 2) / 256, 256>>>(out);
}

// round 10
// speedup vs baseline: 2.1174x; 1.0466x over previous
#include <cuda_runtime.h>
#include <cuda_fp16.h>
#include <cstdint>
#include <cstddef>

// out[b,o] = sum_kk A[b,kk]*W[o,kk]; A [256x16384] fp32, W [1024x16384] fp32.
// R8: fp16 single-term HMMA, tile 128x256, 512 threads (16 warps, warp tile
// 64x32) for latency hiding, split-K=16, cp.async dbuf + SMEM convert dbuf,
// MLP-16 batched reduce.

#define BATCH   256
#define COUT    1024
#define KTOT    16384
#define TM      128
#define TN      256
#define NSPLIT  16
#define KLEN    (KTOT / NSPLIT)   // 1024
#define CHUNK   32
#define NCHUNK  (KLEN / CHUNK)    // 32
#define NTHREADS 512

__device__ float g_part[NSPLIT][BATCH * COUT];

// ---- SMEM layout ----
// raw fp32 stage s (2): A 128x32 (16K) + B 256x32 (32K) = 48K
// fp16 stage s (2): Ah 8K | Bh 16K = 24K
#define RAW_STAGE 49152
#define RAW_A(s)  ((s) * RAW_STAGE)
#define RAW_B(s)  ((s) * RAW_STAGE + 16384)
#define BF_BASE   98304
#define BF_STAGE  24576
#define BF_AH(s)  (BF_BASE + (s) * BF_STAGE)
#define BF_BH(s)  (BF_AH(s) + 8192)
#define SMEM_TOTAL (BF_BASE + 2 * BF_STAGE)   // 147456

// 64B-row swizzle (Swizzle<2,4,3>): bits[5:4] ^= bits[8:7]
#define SWZ64(o) ((o) ^ (((o) >> 3) & 0x30))

__device__ __forceinline__ uint32_t smem_u32(const void* p) {
    uint32_t a;
    asm("{ .reg .u64 t; cvta.to.shared.u64 t, %1; cvt.u32.u64 %0, t; }"
        : "=r"(a) : "l"(p));
    return a;
}

__device__ __forceinline__ void cpa16(uint32_t dst, const void* src) {
    asm volatile("cp.async.cg.shared.global [%0], [%1], 16;"
                 :: "r"(dst), "l"(src) : "memory");
}
#define CP_COMMIT() asm volatile("cp.async.commit_group;" ::: "memory")
#define CP_WAIT1()  asm volatile("cp.async.wait_group 1;" ::: "memory")

__device__ __forceinline__ void ldsm4(uint32_t& r0, uint32_t& r1, uint32_t& r2,
                                      uint32_t& r3, uint32_t addr) {
    asm volatile("ldmatrix.sync.aligned.m8n8.x4.shared.b16 {%0,%1,%2,%3}, [%4];"
                 : "=r"(r0), "=r"(r1), "=r"(r2), "=r"(r3) : "r"(addr));
}

__device__ __forceinline__ void mma16816(float& c0, float& c1, float& c2, float& c3,
                                         uint32_t a0, uint32_t a1, uint32_t a2,
                                         uint32_t a3, uint32_t b0, uint32_t b1) {
    asm volatile(
        "mma.sync.aligned.m16n8k16.row.col.f32.f16.f16.f32 "
        "{%0,%1,%2,%3}, {%4,%5,%6,%7}, {%8,%9}, {%0,%1,%2,%3};"
        : "+f"(c0), "+f"(c1), "+f"(c2), "+f"(c3)
        : "r"(a0), "r"(a1), "r"(a2), "r"(a3), "r"(b0), "r"(b1));
}

// fp32 pair -> fp16x2 (RN)
__device__ __forceinline__ uint32_t cvt_pair_h(float x0, float x1) {
    uint32_t hi;
    asm("cvt.rn.f16x2.f32 %0, %1, %2;" : "=r"(hi) : "f"(x1), "f"(x0));
    return hi;
}

// Issue cp.asyncs for chunk ich into raw stage s.
// Thread t owns rows (t>>3) + 64j, float4 column t&7.
__device__ __forceinline__ void load_raw(const float* __restrict__ Abase,
                                         const float* __restrict__ Wbase,
                                         uint32_t sb, int s, int ich, int tid) {
    uint32_t ra = sb + (uint32_t)RAW_A(s);
    uint32_t rb = sb + (uint32_t)RAW_B(s);
    int r0 = tid >> 3, c4 = tid & 7;          // r0: 0..63
    const float* Ap = Abase + (size_t)ich * CHUNK + (size_t)r0 * KTOT + c4 * 4;
#pragma unroll
    for (int j = 0; j < 2; j++)
        cpa16(ra + (uint32_t)((r0 + 64 * j) * 128 + c4 * 16),
              Ap + (size_t)(64 * j) * KTOT);
    const float* Wp = Wbase + (size_t)ich * CHUNK + (size_t)r0 * KTOT + c4 * 4;
#pragma unroll
    for (int j = 0; j < 4; j++)
        cpa16(rb + (uint32_t)((r0 + 64 * j) * 128 + c4 * 16),
              Wp + (size_t)(64 * j) * KTOT);
}

// Convert raw stage s -> fp16 stage s. Each thread converts only data it cp.async'd.
__device__ __forceinline__ void convert_stage(char* smem, int s, int tid) {
    int r0 = tid >> 3, c4 = tid & 7;
    const float4* rawA = (const float4*)(smem + RAW_A(s));
#pragma unroll
    for (int j = 0; j < 2; j++) {
        int r = r0 + 64 * j;
        float4 v = rawA[r * 8 + c4];
        uint32_t h0 = cvt_pair_h(v.x, v.y);
        uint32_t h1 = cvt_pair_h(v.z, v.w);
        uint32_t off = SWZ64((uint32_t)(r * 64 + c4 * 8));
        *(uint2*)(smem + BF_AH(s) + off) = make_uint2(h0, h1);
    }
    const float4* rawB = (const float4*)(smem + RAW_B(s));
#pragma unroll
    for (int j = 0; j < 4; j++) {
        int r = r0 + 64 * j;
        float4 v = rawB[r * 8 + c4];
        uint32_t h0 = cvt_pair_h(v.x, v.y);
        uint32_t h1 = cvt_pair_h(v.z, v.w);
        uint32_t off = SWZ64((uint32_t)(r * 64 + c4 * 8));
        *(uint2*)(smem + BF_BH(s) + off) = make_uint2(h0, h1);
    }
}

__global__ void __launch_bounds__(NTHREADS, 1)
gemm_kernel(const float* __restrict__ A, const float* __restrict__ W) {
    extern __shared__ char smem[];
    uint32_t sb = smem_u32(smem);
    int tid = threadIdx.x;
    int wid = tid >> 5;
    int lane = tid & 31;

    int m0 = blockIdx.x * TM;
    int n0 = blockIdx.y * TN;
    int k0 = blockIdx.z * KLEN;

    int wr = wid & 1;        // warp tile 64x32: row half (2)
    int wc = wid >> 1;       // col eighth (8)

    uint32_t a_row[4], b_row[2];
#pragma unroll
    for (int mt = 0; mt < 4; mt++)
        a_row[mt] = (uint32_t)((wr * 64 + mt * 16 + (lane & 15)) * 64);
#pragma unroll
    for (int p = 0; p < 2; p++)
        b_row[p] = (uint32_t)((wc * 32 + p * 16 + (lane & 7) + ((lane & 16) >> 1)) * 64);
    uint32_t a_csel = (uint32_t)((lane >> 4) * 16);
    uint32_t b_csel = (uint32_t)(((lane >> 3) & 1) * 16);

    float acc[4][4][4];
#pragma unroll
    for (int mt = 0; mt < 4; mt++)
#pragma unroll
        for (int nt = 0; nt < 4; nt++)
#pragma unroll
            for (int r = 0; r < 4; r++) acc[mt][nt][r] = 0.0f;

    const float* Abase = A + (size_t)m0 * KTOT + k0;
    const float* Wbase = W + (size_t)n0 * KTOT + k0;

    // Prologue: prefetch chunks 0,1; convert chunk 0.
    load_raw(Abase, Wbase, sb, 0, 0, tid);
    CP_COMMIT();
    load_raw(Abase, Wbase, sb, 1, 1, tid);
    CP_COMMIT();
    CP_WAIT1();
    convert_stage(smem, 0, tid);
    __syncthreads();

    for (int i = 0; i < NCHUNK; i++) {
        int s = i & 1;
        if (i + 2 < NCHUNK) load_raw(Abase, Wbase, sb, s, i + 2, tid);
        CP_COMMIT();

        uint32_t bfa = sb + (uint32_t)BF_AH(s);
        uint32_t bfb = sb + (uint32_t)BF_BH(s);

#pragma unroll
        for (int ks = 0; ks < 2; ks++) {
            uint32_t acsel = (uint32_t)(ks * 32) + a_csel;
            uint32_t bcsel = (uint32_t)(ks * 32) + b_csel;
            uint32_t ah[4][4], bh[2][4];

#pragma unroll
            for (int mt = 0; mt < 4; mt++)
                ldsm4(ah[mt][0], ah[mt][1], ah[mt][2], ah[mt][3],
                      bfa + SWZ64(a_row[mt] + acsel));
#pragma unroll
            for (int p = 0; p < 2; p++)
                ldsm4(bh[p][0], bh[p][1], bh[p][2], bh[p][3],
                      bfb + SWZ64(b_row[p] + bcsel));

#pragma unroll
            for (int mt = 0; mt < 4; mt++)
#pragma unroll
                for (int nt = 0; nt < 4; nt++)
                    mma16816(acc[mt][nt][0], acc[mt][nt][1], acc[mt][nt][2],
                             acc[mt][nt][3], ah[mt][0], ah[mt][1], ah[mt][2],
                             ah[mt][3], bh[nt >> 1][(nt & 1) * 2],
                             bh[nt >> 1][(nt & 1) * 2 + 1]);
        }

        if (i + 1 < NCHUNK) {
            CP_WAIT1();
            convert_stage(smem, (i + 1) & 1, tid);
        }
        __syncthreads();
    }

    // Epilogue: write split-K partials.
    {
        float* part = g_part[blockIdx.z];
        int mbase = m0 + wr * 64;
        int nbase = n0 + wc * 32 + 2 * (lane & 3);
        int rowi = lane >> 2;
#pragma unroll
        for (int mt = 0; mt < 4; mt++) {
#pragma unroll
            for (int nt = 0; nt < 4; nt++) {
                int m = mbase + mt * 16 + rowi;
                int n = nbase + nt * 8;
                *(float2*)&part[(size_t)m * COUT + n] =
                    make_float2(acc[mt][nt][0], acc[mt][nt][1]);
                *(float2*)&part[(size_t)(m + 8) * COUT + n] =
                    make_float2(acc[mt][nt][2], acc[mt][nt][3]);
            }
        }
    }
}

// ---------------- deterministic split-K reduction (MLP=16 batched) ----------------
__global__ void __launch_bounds__(256, 1)
reduce_kernel(float* __restrict__ out) {
    int idx = blockIdx.x * blockDim.x + threadIdx.x;  // float2 index, 131072 total
    float2 v[NSPLIT];
#pragma unroll
    for (int s = 0; s < NSPLIT; s++)
        v[s] = ((const float2*)g_part[s])[idx];
    // pairwise tree sum (deterministic, no long dependency chain)
#pragma unroll
    for (int stride = 1; stride < NSPLIT; stride *= 2)
#pragma unroll
        for (int s = 0; s < NSPLIT; s += 2 * stride) {
            v[s].x += v[s + stride].x;
            v[s].y += v[s + stride].y;
        }
    ((float2*)out)[idx] = v[0];
}

extern "C" void kernel_launch(void* const* d_in, const int* in_sizes, int n_in,
                              void* d_out, int out_size) {
    const float* A = (const float*)d_in[0];   // curr_input [256,1024,16]
    const float* W = (const float*)d_in[1];   // weight     [1024,1024,16]
    float* out = (float*)d_out;               // [256,1024]

    cudaFuncSetAttribute(gemm_kernel, cudaFuncAttributeMaxDynamicSharedMemorySize,
                         SMEM_TOTAL);

    dim3 grid(BATCH / TM, COUT / TN, NSPLIT);  // (2, 4, 16) = 128 CTAs
    gemm_kernel<<<grid, NTHREADS, SMEM_TOTAL>>>(A, W);
    reduce_kernel<<<(BATCH * COUT / 2) / 256, 256>>>(out);
}